// round 8
// baseline (speedup 1.0000x reference)
#include <cuda_runtime.h>

#define BATCH 4096
#define NU    20
#define NCOL  120

// Output regions (floats): f1 | g1 | f2 | g2
#define F1OFF 0
#define G1OFF (BATCH * NU)
#define F2OFF (G1OFF + BATCH * NU * NCOL)
#define G2OFF (F2OFF + BATCH * NCOL)

// ---- global scratch (transposed / duplicated weights), set by setup kernel ----
// WBT : [mlp][n32][k16]          @ 0     (1024)
// WCD : [mlp][n16][k32 dup2]     @ 1024  (2048)   stride 64
// WDD : [nrn205][k16 dup2]       @ 3072  (6560)   stride 32
// BDD : [nrn205][2]              @ 9632  (410)
#define WBT_O 0
#define WCD_O 1024
#define WDD_O 3072
#define BDD_O 9632
#define SCR_FLOATS 10044

__device__ __align__(16) float g_scr[SCR_FLOATS];

// ---- shared memory (floats): x halo + activations only ----
#define SXH 0            /* 24: [0]=x[19], [1..20]=x[0..19], [21]=x[0] */
#define HA  24           /* flat  [mlp][site][k16]  : 640 */
#define HBI 664          /* pair  [mlp][sp][k32][2] : 1280 */
#define HCI 1944         /* pair  [mlp][sp][k16][2] : 640 */
#define SMEM_FLOATS 2584

#define PACK2(d, lo, hi) \
    asm("mov.b64 %0, {%1, %2};" : "=l"(d) : "f"(lo), "f"(hi))
#define UNPACK2(lo, hi, s) \
    asm("mov.b64 {%0, %1}, %2;" : "=f"(lo), "=f"(hi) : "l"(s))
#define FMA2(d, a, b, c) \
    asm("fma.rn.f32x2 %0, %1, %2, %3;" : "=l"(d) : "l"(a), "l"(b), "l"(c))

#define DOT16(acc, h4p, w0, w1, w2, w3)                                    \
    {                                                                      \
        float4 h0 = (h4p)[0], h1 = (h4p)[1], h2 = (h4p)[2], h3 = (h4p)[3]; \
        acc += h0.x*w0.x + h0.y*w0.y + h0.z*w0.z + h0.w*w0.w;              \
        acc += h1.x*w1.x + h1.y*w1.y + h1.z*w1.z + h1.w*w1.w;              \
        acc += h2.x*w2.x + h2.y*w2.y + h2.z*w2.z + h2.w*w2.w;              \
        acc += h3.x*w3.x + h3.y*w3.y + h3.z*w3.z + h3.w*w3.w;              \
    }

// ---- one-block setup: build transposed/duplicated weight scratch ----
__global__ void CGN_setup_kernel(
    const float* __restrict__ w1b, const float* __restrict__ w2b,
    const float* __restrict__ w1c, const float* __restrict__ w2c,
    const float* __restrict__ w1d, const float* __restrict__ w2d,
    const float* __restrict__ b1d, const float* __restrict__ b2d)
{
    const int tid = threadIdx.x;
    for (int i = tid; i < 1024; i += 256) {           // b: [m][n32][k16]
        int m = i >> 9, r = i & 511;
        int n = r >> 4, k = r & 15;
        g_scr[WBT_O + i] = (m ? w2b : w1b)[k * 32 + n];
    }
    for (int i = tid; i < 2048; i += 256) {           // c: [m][n16][k32 dup]
        int m = i >> 10, r = i & 1023;
        int n = r >> 6;
        int k = (r >> 1) & 31;
        g_scr[WCD_O + i] = (m ? w2c : w1c)[k * 16 + n];
    }
    for (int i = tid; i < 6560; i += 256) {           // d: [nrn][k16 dup]
        int nrn = i >> 5;
        int k = (i >> 1) & 15;
        g_scr[WDD_O + i] = (nrn < 19) ? w1d[k * 19 + nrn]
                                      : w2d[k * 186 + (nrn - 19)];
    }
    for (int i = tid; i < 205; i += 256) {            // d bias pairs
        float v = (i < 19) ? b1d[i] : b2d[i - 19];
        g_scr[BDD_O + 2 * i]     = v;
        g_scr[BDD_O + 2 * i + 1] = v;
    }
}

__global__ __launch_bounds__(256, 4) void CGN_fused_kernel(
    const float* __restrict__ x,
    const float* __restrict__ w1a, const float* __restrict__ bb1a,
    const float* __restrict__ bb1b, const float* __restrict__ bb1c,
    const float* __restrict__ w2a, const float* __restrict__ bb2a,
    const float* __restrict__ bb2b, const float* __restrict__ bb2c,
    float* __restrict__ out)
{
    __shared__ __align__(16) float sm[SMEM_FLOATS];
    const int tid = threadIdx.x;
    const int b   = blockIdx.x;

    float* g1o = out + G1OFF + (size_t)b * 2400;
    float* g2o = out + G2OFF + (size_t)b * 14400;

    // ---- Phase Z: zero-fill g1 & g2 (pure STG.128) ----
    {
        const float4 z4 = make_float4(0.f, 0.f, 0.f, 0.f);
        float4* p1 = reinterpret_cast<float4*>(g1o);
        for (int q = tid; q < 600; q += 256) p1[q] = z4;
        float4* p2 = reinterpret_cast<float4*>(g2o);
        for (int q = tid; q < 3600; q += 256) p2[q] = z4;
    }

    // ---- x row with halo ----
    if (tid < 20) {
        float v = x[(size_t)b * NU + tid];
        sm[SXH + 1 + tid] = v;
        if (tid == 19) sm[SXH]      = v;
        if (tid == 0)  sm[SXH + 21] = v;
    }
    __syncthreads();

    // ---- Phase A: layer a (3->16), 640 tasks, weights straight from global ----
    for (int t = tid; t < 640; t += 256) {
        int site = t >> 5;
        int n    = t & 31;
        float x0 = sm[SXH + site];
        float x1 = sm[SXH + site + 1];
        float x2 = sm[SXH + site + 2];
        bool m1 = n < 16;
        int  nn = n & 15;
        const float* W = m1 ? w1a : w2a;
        float bias     = m1 ? bb1a[nn] : bb2a[nn];
        float acc = bias + x0 * W[nn] + x1 * W[16 + nn] + x2 * W[32 + nn];
        sm[HA + (m1 ? 0 : 320) + site * 16 + nn] = fmaxf(acc, 0.f);
    }
    __syncthreads();

    // ---- Phase B: layer b (16->32), 256 tasks. w col = 4 LDG.128 from WBT.
    //      stores site-pair interleaved into HBI ----
    {
        int n  = tid & 63;
        int sg = tid >> 6;
        bool m1 = n < 32;
        int  nn = n & 31;
        const float4* wp = reinterpret_cast<const float4*>(
            &g_scr[WBT_O + (m1 ? 0 : 512) + nn * 16]);
        float4 w0 = wp[0], w1 = wp[1], w2 = wp[2], w3 = wp[3];
        float bias = (m1 ? bb1b : bb2b)[nn];
        int hab = HA  + (m1 ? 0 : 320);
        int hbb = HBI + (m1 ? 0 : 640);
        #pragma unroll
        for (int s5 = 0; s5 < 5; s5++) {
            int s = sg * 5 + s5;
            const float4* h4 = reinterpret_cast<const float4*>(&sm[hab + s * 16]);
            float acc = bias;
            DOT16(acc, h4, w0, w1, w2, w3);
            sm[hbb + (s >> 1) * 64 + nn * 2 + (s & 1)] = fmaxf(acc, 0.f);
        }
    }
    __syncthreads();

    // ---- Phase C: layer c (32->16), paired f32x2. 320 tasks (nn16, mlp, sp10).
    //      dup w from WCD (LDG.128), interleaved h (LDS.128) ----
    for (int t = tid; t < 320; t += 256) {
        int nn = t & 15;
        int m  = (t >> 4) & 1;
        int sp = t >> 5;
        const ulonglong2* wd = reinterpret_cast<const ulonglong2*>(
            &g_scr[WCD_O + m * 1024 + nn * 64]);
        const ulonglong2* hd = reinterpret_cast<const ulonglong2*>(
            &sm[HBI + m * 640 + sp * 64]);
        float bias = (m ? bb2c : bb1c)[nn];
        unsigned long long acc2;
        PACK2(acc2, bias, bias);
        #pragma unroll
        for (int j = 0; j < 16; j++) {
            ulonglong2 wv = wd[j];
            ulonglong2 hv = hd[j];
            FMA2(acc2, wv.x, hv.x, acc2);
            FMA2(acc2, wv.y, hv.y, acc2);
        }
        float lo, hi;
        UNPACK2(lo, hi, acc2);
        sm[HCI + m * 320 + sp * 32 + nn * 2]     = fmaxf(lo, 0.f);
        sm[HCI + m * 320 + sp * 32 + nn * 2 + 1] = fmaxf(hi, 0.f);
    }
    __syncthreads();

    // ---- Phase D: output layer + banded scatter, paired f32x2.
    //      One neuron per thread (tid<205); dup w column cached once (8x16B);
    //      10 site-pairs, incremental band-column math. ----
    if (tid < 205) {
        const int nrn = tid;
        bool is1 = nrn < 19;
        int m = nrn - 19;

        const ulonglong2* wdp = reinterpret_cast<const ulonglong2*>(
            &g_scr[WDD_O + nrn * 32]);
        ulonglong2 w[8];
        #pragma unroll
        for (int j = 0; j < 8; j++) w[j] = wdp[j];
        unsigned long long bias2 =
            *reinterpret_cast<const unsigned long long*>(&g_scr[BDD_O + nrn * 2]);

        int cls, zq = 0, col = 0;
        if (is1) {
            if (nrn == 0) cls = 0;
            else {
                cls = 1;
                col = 114 + (nrn - 1);            // ((0+19)%20)*6 + j
                if (col >= 120) col -= 120;
            }
        } else if (m < 6) {
            cls = 2;
        } else {
            cls = 3;
            zq = (m - 6) / 30;
            int jq = (m - 6) - zq * 30;
            col = 108 + jq;                        // ((0+18)%20)*6 + j
            if (col >= 120) col -= 120;
        }

        int hcb = HCI + (is1 ? 0 : 320);
        #pragma unroll
        for (int p = 0; p < 10; p++) {
            const ulonglong2* hd = reinterpret_cast<const ulonglong2*>(&sm[hcb + p * 32]);
            unsigned long long acc2 = bias2;
            #pragma unroll
            for (int j = 0; j < 8; j++) {
                ulonglong2 hv = hd[j];
                FMA2(acc2, w[j].x, hv.x, acc2);
                FMA2(acc2, w[j].y, hv.y, acc2);
            }
            float aA, aB;
            UNPACK2(aA, aB, acc2);
            int s = 2 * p;
            if (cls == 0) {
                out[(size_t)b * NU + s]     = aA;
                out[(size_t)b * NU + s + 1] = aB;
            } else if (cls == 1) {
                g1o[s * 120 + col] = aA;       col += 6; if (col >= 120) col -= 120;
                g1o[(s + 1) * 120 + col] = aB; col += 6; if (col >= 120) col -= 120;
            } else if (cls == 2) {
                out[F2OFF + (size_t)b * NCOL + s * 6 + m]       = aA;
                out[F2OFF + (size_t)b * NCOL + (s + 1) * 6 + m] = aB;
            } else {
                g2o[(s * 6 + zq) * 120 + col] = aA;       col += 6; if (col >= 120) col -= 120;
                g2o[((s + 1) * 6 + zq) * 120 + col] = aB; col += 6; if (col >= 120) col -= 120;
            }
        }
    }
}

extern "C" void kernel_launch(void* const* d_in, const int* in_sizes, int n_in,
                              void* d_out, int out_size) {
    const float* x   = (const float*)d_in[0];
    const float* w1a = (const float*)d_in[1];
    const float* b1a = (const float*)d_in[2];
    const float* w1b = (const float*)d_in[3];
    const float* b1b = (const float*)d_in[4];
    const float* w1c = (const float*)d_in[5];
    const float* b1c = (const float*)d_in[6];
    const float* w1d = (const float*)d_in[7];
    const float* b1d = (const float*)d_in[8];
    const float* w2a = (const float*)d_in[9];
    const float* b2a = (const float*)d_in[10];
    const float* w2b = (const float*)d_in[11];
    const float* b2b = (const float*)d_in[12];
    const float* w2c = (const float*)d_in[13];
    const float* b2c = (const float*)d_in[14];
    const float* w2d = (const float*)d_in[15];
    const float* b2d = (const float*)d_in[16];

    CGN_setup_kernel<<<1, 256>>>(w1b, w2b, w1c, w2c, w1d, w2d, b1d, b2d);
    CGN_fused_kernel<<<BATCH, 256>>>(
        x, w1a, b1a, b1b, b1c,
        w2a, b2a, b2b, b2c,
        (float*)d_out);
}

// round 10
// speedup vs baseline: 1.9216x; 1.9216x over previous
#include <cuda_runtime.h>

#define BATCH 4096
#define NU    20
#define DZ    6
#define NCOL  120

// Output regions (floats): f1 | g1 | f2 | g2
#define F1OFF 0
#define G1OFF (BATCH * NU)
#define F2OFF (G1OFF + BATCH * NU * NCOL)
#define G2OFF (F2OFF + BATCH * NCOL)

// Shared-memory float offsets (all buffers 16B-aligned)
#define W1A 0
#define B1A 48
#define W1B 64
#define B1B 576
#define W1C 608
#define B1C 1120
#define W2A 1136
#define B2A 1184
#define W2B 1200
#define B2B 1712
#define W2C 1744
#define B2C 2256
#define SXH 2272        /* 24: [0]=x[19], [1..20]=x[0..19], [21]=x[0] */
#define HA1 2296        /* 20*16 */
#define HA2 2632        /* +336 pad => bank-disjoint halves */
#define HC1 HA1
#define HC2 HA2
#define HB1 2952        /* 20*32 */
#define HB2 3592
#define SMEM_FLOATS 4232

// two-chain dot product: halves RAW dependency depth
#define DOT16_2(acc, h4p, w0, w1, w2, w3)                                   \
    {                                                                       \
        float4 h0 = (h4p)[0], h1 = (h4p)[1], h2 = (h4p)[2], h3 = (h4p)[3];  \
        float a0 = h0.x*w0.x + h0.y*w0.y + h0.z*w0.z + h0.w*w0.w            \
                 + h1.x*w1.x + h1.y*w1.y + h1.z*w1.z + h1.w*w1.w;           \
        float a1 = h2.x*w2.x + h2.y*w2.y + h2.z*w2.z + h2.w*w2.w            \
                 + h3.x*w3.x + h3.y*w3.y + h3.z*w3.z + h3.w*w3.w;           \
        acc += a0 + a1;                                                     \
    }

__global__ __launch_bounds__(256, 4) void CGN_fused_kernel(
    const float* __restrict__ x,
    const float* __restrict__ w1a, const float* __restrict__ bb1a,
    const float* __restrict__ w1b, const float* __restrict__ bb1b,
    const float* __restrict__ w1c, const float* __restrict__ bb1c,
    const float* __restrict__ w1d, const float* __restrict__ bb1d,
    const float* __restrict__ w2a, const float* __restrict__ bb2a,
    const float* __restrict__ w2b, const float* __restrict__ bb2b,
    const float* __restrict__ w2c, const float* __restrict__ bb2c,
    const float* __restrict__ w2d, const float* __restrict__ bb2d,
    float* __restrict__ out)
{
    __shared__ __align__(16) float sm[SMEM_FLOATS];
    const int tid = threadIdx.x;
    const int b   = blockIdx.x;

    float* g1o = out + G1OFF + (size_t)b * (NU * NCOL);
    float* g2o = out + G2OFF + (size_t)b * (NCOL * NCOL);

    // ---- Phase Z: zero-fill g1 & g2 with pure wide stores ----
    {
        const float4 z4 = make_float4(0.f, 0.f, 0.f, 0.f);
        float4* p1 = reinterpret_cast<float4*>(g1o);
        for (int q = tid; q < 600; q += 256) p1[q] = z4;
        float4* p2 = reinterpret_cast<float4*>(g2o);
        for (int q = tid; q < 3600; q += 256) p2[q] = z4;
    }

    // ---- stage abc-layer weights + x row (halo) into smem ----
    #define CP(off, src, n) for (int i = tid; i < (n); i += 256) sm[(off) + i] = (src)[i];
    CP(W1A, w1a, 48)   CP(B1A, bb1a, 16)
    CP(W1B, w1b, 512)  CP(B1B, bb1b, 32)
    CP(W1C, w1c, 512)  CP(B1C, bb1c, 16)
    CP(W2A, w2a, 48)   CP(B2A, bb2a, 16)
    CP(W2B, w2b, 512)  CP(B2B, bb2b, 32)
    CP(W2C, w2c, 512)  CP(B2C, bb2c, 16)
    #undef CP
    if (tid < 20) {
        float v = x[(size_t)b * NU + tid];
        sm[SXH + 1 + tid] = v;
        if (tid == 19) sm[SXH]      = v;
        if (tid == 0)  sm[SXH + 21] = v;
    }
    __syncthreads();

    // ---- Phase A: layer a (3 -> 16), both MLPs, 20 sites. 640 tasks ----
    for (int task = tid; task < 640; task += 256) {
        int site = task >> 5;
        int n    = task & 31;
        float x0 = sm[SXH + site];
        float x1 = sm[SXH + site + 1];
        float x2 = sm[SXH + site + 2];
        bool m1 = n < 16;
        int  nn = n & 15;
        const float* W = m1 ? &sm[W1A] : &sm[W2A];
        float bias     = m1 ? sm[B1A + nn] : sm[B2A + nn];
        float acc = bias + x0 * W[nn] + x1 * W[16 + nn] + x2 * W[32 + nn];
        sm[(m1 ? HA1 : HA2) + site * 16 + nn] = fmaxf(acc, 0.f);
    }
    __syncthreads();

    // ---- Phase B: layer b (16 -> 32). 256 tasks: 64 neurons x 4 site-groups ----
    {
        int n  = tid & 63;
        int sg = tid >> 6;
        bool m1 = n < 32;
        int  nn = n & 31;
        const float* W = m1 ? &sm[W1B] : &sm[W2B];
        float bias     = m1 ? sm[B1B + nn] : sm[B2B + nn];
        float w[16];
        #pragma unroll
        for (int k = 0; k < 16; k++) w[k] = W[k * 32 + nn];
        float4 w0 = make_float4(w[0],  w[1],  w[2],  w[3]);
        float4 w1 = make_float4(w[4],  w[5],  w[6],  w[7]);
        float4 w2 = make_float4(w[8],  w[9],  w[10], w[11]);
        float4 w3 = make_float4(w[12], w[13], w[14], w[15]);
        int ha = m1 ? HA1 : HA2;
        int hb = m1 ? HB1 : HB2;
        #pragma unroll
        for (int s5 = 0; s5 < 5; s5++) {
            int s = sg * 5 + s5;
            const float4* h4 = reinterpret_cast<const float4*>(&sm[ha + s * 16]);
            float acc = bias;
            DOT16_2(acc, h4, w0, w1, w2, w3);
            sm[hb + s * 32 + nn] = fmaxf(acc, 0.f);
        }
    }
    __syncthreads();

    // ---- Phase C: layer c (32 -> 16). 640 tasks, float4 h reads, 2 chains ----
    for (int task = tid; task < 640; task += 256) {
        int site = task >> 5;
        int n    = task & 31;
        bool m1 = n < 16;
        int  nn = m1 ? n : n - 16;
        const float* W = m1 ? &sm[W1C] : &sm[W2C];
        float bias     = m1 ? sm[B1C + nn] : sm[B2C + nn];
        const float4* h4 = reinterpret_cast<const float4*>(&sm[(m1 ? HB1 : HB2) + site * 32]);
        float a0 = bias, a1 = 0.f;
        #pragma unroll
        for (int k8 = 0; k8 < 4; k8++) {
            float4 ha_ = h4[k8];
            float4 hb_ = h4[k8 + 4];
            a0 += ha_.x * W[(4 * k8 + 0) * 16 + nn];
            a0 += ha_.y * W[(4 * k8 + 1) * 16 + nn];
            a0 += ha_.z * W[(4 * k8 + 2) * 16 + nn];
            a0 += ha_.w * W[(4 * k8 + 3) * 16 + nn];
            a1 += hb_.x * W[(4 * k8 + 16) * 16 + nn];
            a1 += hb_.y * W[(4 * k8 + 17) * 16 + nn];
            a1 += hb_.z * W[(4 * k8 + 18) * 16 + nn];
            a1 += hb_.w * W[(4 * k8 + 19) * 16 + nn];
        }
        sm[(m1 ? HC1 : HC2) + site * 16 + nn] = fmaxf(a0 + a1, 0.f);
    }
    __syncthreads();

    // ---- Phase D: output layer fused with banded scatter.
    //      820 groups = 205 neurons x 4 site-groups (5 sites each). ----
    for (int g = tid; g < 820; g += 256) {
        int nrn = g % 205;
        int sg  = g / 205;
        int s0  = sg * 5;
        bool is1 = nrn < 19;
        float w[16], bias;
        int m = 0;
        if (is1) {
            #pragma unroll
            for (int k = 0; k < 16; k++) w[k] = w1d[k * 19 + nrn];
            bias = bb1d[nrn];
        } else {
            m = nrn - 19;
            #pragma unroll
            for (int k = 0; k < 16; k++) w[k] = w2d[k * 186 + m];
            bias = bb2d[m];
        }
        float4 w0 = make_float4(w[0],  w[1],  w[2],  w[3]);
        float4 w1 = make_float4(w[4],  w[5],  w[6],  w[7]);
        float4 w2 = make_float4(w[8],  w[9],  w[10], w[11]);
        float4 w3 = make_float4(w[12], w[13], w[14], w[15]);

        int cls, zq = 0, col = 0;
        if (is1) {
            if (nrn == 0) cls = 0;
            else {
                cls = 1;
                col = ((s0 + 19) % 20) * 6 + (nrn - 1);
                if (col >= 120) col -= 120;
            }
        } else if (m < 6) {
            cls = 2;
        } else {
            cls = 3;
            zq = (m - 6) / 30;
            int jq = (m - 6) - zq * 30;
            col = ((s0 + 18) % 20) * 6 + jq;
            if (col >= 120) col -= 120;
        }

        int hc = is1 ? HC1 : HC2;
        #pragma unroll
        for (int s5 = 0; s5 < 5; s5++) {
            int s = s0 + s5;
            const float4* h4 = reinterpret_cast<const float4*>(&sm[hc + s * 16]);
            float acc = bias;
            DOT16_2(acc, h4, w0, w1, w2, w3);
            if (cls == 0) {
                out[F1OFF + (size_t)b * NU + s] = acc;
            } else if (cls == 1) {
                g1o[s * 120 + col] = acc;
                col += 6; if (col >= 120) col -= 120;
            } else if (cls == 2) {
                out[F2OFF + (size_t)b * NCOL + s * 6 + m] = acc;
            } else {
                g2o[(s * 6 + zq) * 120 + col] = acc;
                col += 6; if (col >= 120) col -= 120;
            }
        }
    }
}

extern "C" void kernel_launch(void* const* d_in, const int* in_sizes, int n_in,
                              void* d_out, int out_size) {
    const float* x   = (const float*)d_in[0];
    const float* w1a = (const float*)d_in[1];
    const float* b1a = (const float*)d_in[2];
    const float* w1b = (const float*)d_in[3];
    const float* b1b = (const float*)d_in[4];
    const float* w1c = (const float*)d_in[5];
    const float* b1c = (const float*)d_in[6];
    const float* w1d = (const float*)d_in[7];
    const float* b1d = (const float*)d_in[8];
    const float* w2a = (const float*)d_in[9];
    const float* b2a = (const float*)d_in[10];
    const float* w2b = (const float*)d_in[11];
    const float* b2b = (const float*)d_in[12];
    const float* w2c = (const float*)d_in[13];
    const float* b2c = (const float*)d_in[14];
    const float* w2d = (const float*)d_in[15];
    const float* b2d = (const float*)d_in[16];

    CGN_fused_kernel<<<BATCH, 256>>>(
        x, w1a, b1a, w1b, b1b, w1c, b1c, w1d, b1d,
        w2a, b2a, w2b, b2b, w2c, b2c, w2d, b2d,
        (float*)d_out);
}